// round 16
// baseline (speedup 1.0000x reference)
#include <cuda_runtime.h>
#include <math.h>
#include <stdint.h>

#define B 2
#define H 16
#define W 4000
#define PLANE (H*W)
#define NPIX (B*PLANE)
#define CDT 80
#define NFLOW 8
#define NLAYER 8
typedef unsigned long long u64;
typedef unsigned int u32;

// smem layout (floats): [R1 9728][SML 8704][BIG 8704] = 27136 floats = 108544 B
#define SA 152
#define SB 136
#define SC 136
#define SMLF 9728
#define BIGF 18432
#define SMEMF 27136

// ---------------- helpers ----------------
__device__ __forceinline__ u32 smem_u32(const void* p) {
    u32 a; asm("{ .reg .u64 t; cvta.to.shared.u64 t, %1; cvt.u32.u64 %0, t; }" : "=r"(a) : "l"(p));
    return a;
}
__device__ __forceinline__ float tf32r(float x) {
    u32 r; asm("cvt.rna.tf32.f32 %0, %1;" : "=r"(r) : "f"(x));
    return __uint_as_float(r);
}
__device__ __forceinline__ u64 dup2(float x) { u64 r; asm("mov.b64 %0, {%1, %1};" : "=l"(r) : "f"(x)); return r; }
__device__ __forceinline__ void ffma2(u64& d, u64 a, u64 b) { asm("fma.rn.f32x2 %0, %1, %2, %0;" : "+l"(d) : "l"(a), "l"(b)); }
__device__ __forceinline__ void unpk(u64 v, float& lo, float& hi) { asm("mov.b64 {%0, %1}, %2;" : "=f"(lo), "=f"(hi) : "l"(v)); }

#define CPA16(d, s)     asm volatile("cp.async.cg.shared.global [%0], [%1], 16;" :: "r"(d), "l"(s) : "memory")
#define CPA16Z(d, s, z) asm volatile("cp.async.cg.shared.global [%0], [%1], 16, %2;" :: "r"(d), "l"(s), "r"(z) : "memory")
#define CP_COMMIT() asm volatile("cp.async.commit_group;" ::: "memory")
#define CP_WAIT1()  asm volatile("cp.async.wait_group 1;" ::: "memory")
#define CP_WAIT0()  asm volatile("cp.async.wait_group 0;" ::: "memory")

__device__ __forceinline__ void mma8(float* d, const u32* a, u32 b0, u32 b1) {
    asm("mma.sync.aligned.m16n8k8.row.col.f32.tf32.tf32.f32 "
        "{%0,%1,%2,%3}, {%4,%5,%6,%7}, {%8,%9}, {%0,%1,%2,%3};"
        : "+f"(d[0]), "+f"(d[1]), "+f"(d[2]), "+f"(d[3])
        : "r"(a[0]), "r"(a[1]), "r"(a[2]), "r"(a[3]), "r"(b0), "r"(b1));
}

__device__ __forceinline__ void gemm_k8(float (&acc)[4][4][4],
    const float* As, int sa, const float* Bs, int k0, int pm, int pn, int gid, int tg)
{
    u32 a[4][4];
    const float* ar = As + (k0 + tg) * sa;
    #pragma unroll
    for (int ms = 0; ms < 4; ms++) {
        const float* ap = ar + pm + ms*16 + gid;
        a[ms][0] = __float_as_uint(ap[0]);
        a[ms][1] = __float_as_uint(ap[8]);
        a[ms][2] = __float_as_uint(ap[4*sa]);
        a[ms][3] = __float_as_uint(ap[4*sa + 8]);
    }
    const float* br = Bs + (k0 + tg) * SB + pn + gid;
    #pragma unroll
    for (int ns = 0; ns < 4; ns++) {
        u32 b0 = __float_as_uint(br[ns*8]);
        u32 b1 = __float_as_uint(br[ns*8 + 4*SB]);
        #pragma unroll
        for (int ms = 0; ms < 4; ms++) mma8(acc[ms][ns], a[ms], b0, b1);
    }
}

// ---------------- persistent scratch ----------------
__device__ __align__(16) float g_res2[2][B*64*PLANE];
__device__ __align__(16) float g_resT[2][B*64*PLANE];
__device__ __align__(16) float g_skp[B*64*PLANE];
__device__ __align__(16) float g_xbuf[2][NPIX];
__device__ __align__(16) float g_cT [B*CDT*PLANE];
__device__ __align__(16) float g_wT [NFLOW*NLAYER*64*9*128];
__device__ __align__(16) float g_cwT[NFLOW*NLAYER*CDT*128];
__device__ __align__(16) float g_uwT[NFLOW*NLAYER*64*128];

#define N1 (NFLOW*NLAYER*64*9*128)
#define N2 (NFLOW*NLAYER*CDT*128)
#define N3 (NFLOW*NLAYER*64*128)
#define NC (B*CDT*PLANE)

// g-column interleave: tanh ci -> 2ci, sigmoid ci -> 2ci+1
__device__ __forceinline__ int gperm(int co) { return (co < 64) ? 2*co : 2*(co - 64) + 1; }

__global__ void prep_weights(const float* __restrict__ iw, const float* __restrict__ cw,
                             const float* __restrict__ rw, const float* __restrict__ sw,
                             const float* __restrict__ cfull)
{
    long idx = (long)blockIdx.x * 256 + threadIdx.x;
    if (idx < N1) {
        int co  = (int)(idx & 127);
        long t  = idx >> 7;
        int tap = (int)(t % 9); t /= 9;
        int ci  = (int)(t & 63);
        int fl  = (int)(t >> 6);
        int kh = tap / 3, kw = tap % 3;
        long base = idx - co;
        g_wT[base + gperm(co)] = tf32r(iw[((((long)fl*128 + co)*64 + ci)*3 + kh)*3 + kw]);
    } else if (idx < N1 + N2) {
        long i2 = idx - N1;
        int co = (int)(i2 & 127);
        long t = i2 >> 7;
        int ci = (int)(t % CDT);
        int fl = (int)(t / CDT);
        long base = i2 - co;
        g_cwT[base + gperm(co)] = tf32r(cw[((long)fl*128 + co)*CDT + ci]);
    } else if (idx < N1 + N2 + N3) {
        long i3 = idx - N1 - N2;
        int o  = (int)(i3 & 127);
        long t = i3 >> 7;
        int ci = (int)(t & 63);
        int fl = (int)(t >> 6);
        g_uwT[i3] = tf32r((o < 64) ? rw[((long)fl*64 + o)*64 + ci]
                                   : sw[((long)fl*64 + (o-64))*64 + ci]);
    } else if (idx < N1 + N2 + N3 + NC) {
        long i4 = idx - N1 - N2 - N3;
        g_cT[i4] = tf32r(cfull[i4]);
    }
}

// ---------------- first conv ----------------
__global__ void __launch_bounds__(256) first_conv(const float* __restrict__ fw,
                                                  const float* __restrict__ xext, int flow)
{
    __shared__ float fsh[128];
    if (threadIdx.x < 128) fsh[threadIdx.x] = fw[threadIdx.x];
    __syncthreads();
    int pix = blockIdx.x * 256 + threadIdx.x;
    if (pix >= NPIX) return;
    int b = pix / PLANE, rem = pix - b * PLANE, h = rem / W, w = rem - (rem / W) * W;
    const float* xs = (flow == 0) ? xext : g_xbuf[(flow + 1) & 1];
    float x2 = (h >= 2) ? xs[pix - 2*W] : 0.f;
    float x1 = (h >= 1) ? xs[pix - W]   : 0.f;
    #pragma unroll 4
    for (int o = 0; o < 64; o++) {
        float v = tanhf(fsh[2*o]*x2 + fsh[2*o+1]*x1);
        int idx = ((b*64 + o)*H + h)*W + w;
        g_res2[0][idx] = v;
        g_resT[0][idx] = tf32r(v);
        g_skp[idx] = 0.f;
    }
}

// ---------------- fused layer: warp-MMA tf32, live-tap-only pipeline ----------------
template<int D>
__global__ void __launch_bounds__(256, 2) layer_kernel(int flow, int fl, int rb)
{
    extern __shared__ __align__(16) float sh[];
    const int tid = threadIdx.x, lane = tid & 31, wq = tid >> 5;
    const int b = blockIdx.y >> 4, h = blockIdx.y & 15;
    const int w0 = blockIdx.x * 128;
    const int pm = (wq & 1) * 64, pn = (wq >> 1) * 32;
    const int gid = lane >> 2, tg = lane & 3;
    const float* rin  = g_res2[rb];
    const float* rinT = g_resT[rb];
    float* rout  = g_res2[rb ^ 1];
    float* routT = g_resT[rb ^ 1];
    const u32 shb = smem_u32(sh);

    const float* wA = g_wT + (long)fl*73728;
    const float* wC = g_cwT + (long)fl*10240;
    const float* wU = g_uwT + (long)fl*8192;

    int hm = h;
    #pragma unroll 1
    for (int j = flow - 1; j >= 0; j--)
        hm = (j < 4) ? (15 - hm) : (hm < 8 ? 7 - hm : 23 - hm);

    auto stage_w = [&](u32 dst_off, const float* src, int sstr, int rows) {
        u32 dstb = shb + dst_off * 4;
        int nq = rows * 32;
        for (int q = tid; q < nq; q += 256) {
            int ci = q >> 5, jj = q & 31;
            CPA16(dstb + (u32)(ci*SB + jj*4)*4, src + (long)ci*sstr + jj*4);
        }
        CP_COMMIT();
    };
    auto stage_A = [&](int hs) {     // caller guarantees hs >= 0
        #pragma unroll 3
        for (int q = tid; q < 2304; q += 256) {
            int ci = q / 36, j = q - (q / 36) * 36;
            int wg = w0 + j*4 - 8;
            bool ok = (unsigned)wg < (unsigned)W;
            const float* src = rinT + ((long)(b*64 + ci)*H + hs)*W + (ok ? wg : 0);
            u32 z = ok ? 16u : 0u;
            CPA16Z(shb + (u32)(ci*SA + j*4)*4, src, z);
        }
        CP_COMMIT();
    };
    auto stage_acts = [&](int ci0) {
        #pragma unroll 3
        for (int q = tid; q < 1280; q += 256) {
            int ci = q >> 5, j = q & 31;
            int wg = w0 + j*4;
            bool ok = wg < W;
            const float* src = g_cT + ((long)(b*CDT + ci0 + ci)*H + hm)*W + (ok ? wg : 0);
            u32 z = ok ? 16u : 0u;
            CPA16Z(shb + (u32)(ci*SC + j*4)*4, src, z);
        }
        CP_COMMIT();
    };

    const u32 slots[2] = {SMLF, BIGF};

    float acc[4][4][4];
    #pragma unroll
    for (int ms = 0; ms < 4; ms++)
        #pragma unroll
        for (int ns = 0; ns < 4; ns++)
            #pragma unroll
            for (int q = 0; q < 4; q++) acc[ms][ns][q] = 0.f;

    // live conv rows only (h is block-uniform -> no divergence)
    int rlist[3]; int nlive = 0;
    #pragma unroll
    for (int r = 0; r < 3; r++)
        if (h - (2 - r) * D >= 0) rlist[nlive++] = r;
    const int L = 3 * nlive;   // live taps; >= 3 always (r=2 live)

    stage_A(h - (2 - rlist[0]) * D);
    stage_w(slots[0], wA + (long)(3*rlist[0]) * 128, 1152, 64);

    // -------- live conv taps --------
    #pragma unroll 1
    for (int li = 0; li < L; li++) {
        int rr = rlist[li / 3], kw = li - (li / 3) * 3;
        if (li < L - 1) {
            int lj = li + 1;
            int tapj = 3 * rlist[lj / 3] + (lj - (lj / 3) * 3);
            stage_w(slots[lj & 1], wA + (long)tapj * 128, 1152, 64);
        } else {
            stage_w(slots[L & 1], wC, 128, 40);          // cond W half 1
        }
        CP_WAIT1();
        __syncthreads();
        {
            const float* As = sh + (kw - 1)*D + 8;
            const float* Bs = sh + slots[li & 1];
            #pragma unroll 2
            for (int kc = 0; kc < 8; kc++) gemm_k8(acc, As, SA, Bs, kc*8, pm, pn, gid, tg);
        }
        __syncthreads();
        if (kw == 2 && (li / 3) + 1 < nlive)
            stage_A(h - (2 - rlist[li/3 + 1]) * D);
        (void)rr;
    }

    // -------- conditioner (K=80), two 40-row halves --------
    stage_acts(0);
    stage_w(slots[(L + 1) & 1], wC + 40*128, 128, 40);   // cond W half 2
    CP_WAIT1();
    __syncthreads();
    #pragma unroll 1
    for (int kc = 0; kc < 5; kc++) gemm_k8(acc, sh, SC, sh + slots[L & 1], kc*8, pm, pn, gid, tg);
    __syncthreads();
    stage_acts(40);
    stage_w(slots[L & 1], wU, 128, 64);                  // update W
    CP_WAIT1();
    __syncthreads();
    #pragma unroll 1
    for (int kc = 5; kc < 10; kc++) gemm_k8(acc, sh, SC, sh + slots[(L + 1) & 1], kc*8 - 40, pm, pn, gid, tg);
    __syncthreads();

    // -------- gate in registers: c-frags hold (tanh, sigmoid) pairs --------
    #pragma unroll
    for (int ms = 0; ms < 4; ms++)
        #pragma unroll
        for (int ns = 0; ns < 4; ns++) {
            int px0 = pm + ms*16 + gid;
            int p   = (pn >> 1) + ns*4 + tg;
            float t0 = acc[ms][ns][0], s0 = acc[ms][ns][1];
            float t1 = acc[ms][ns][2], s1 = acc[ms][ns][3];
            float v0 = (1.f - __fdividef(2.f, 1.f + __expf(2.f*t0))) *
                       __fdividef(1.f, 1.f + __expf(-s0));
            float v1 = (1.f - __fdividef(2.f, 1.f + __expf(2.f*t1))) *
                       __fdividef(1.f, 1.f + __expf(-s1));
            sh[p*SC + px0]     = tf32r(v0);
            sh[p*SC + px0 + 8] = tf32r(v1);
            acc[ms][ns][0] = acc[ms][ns][1] = acc[ms][ns][2] = acc[ms][ns][3] = 0.f;
        }
    CP_WAIT0();                              // update weights arrived
    __syncthreads();

    // -------- update GEMM: D2[px][o] = act @ [rw|sw] --------
    #pragma unroll 2
    for (int kc = 0; kc < 8; kc++) gemm_k8(acc, sh, SC, sh + slots[L & 1], kc*8, pm, pn, gid, tg);
    __syncthreads();
    float* d2 = sh + SMLF;
    #pragma unroll
    for (int ms = 0; ms < 4; ms++)
        #pragma unroll
        for (int ns = 0; ns < 4; ns++) {
            int px0 = pm + ms*16 + gid, co0 = pn + ns*8 + tg*2;
            d2[co0*SC + px0]         = acc[ms][ns][0];
            d2[(co0+1)*SC + px0]     = acc[ms][ns][1];
            d2[co0*SC + px0 + 8]     = acc[ms][ns][2];
            d2[(co0+1)*SC + px0 + 8] = acc[ms][ns][3];
        }
    __syncthreads();

    // writeout
    {
        int co = tid >> 1;
        int ph = (tid & 1) * 64;
        int ch = co & 63;
        long gb = ((long)(b*64 + ch)*H + h)*W + w0 + ph;
        const float4* dp = (const float4*)(d2 + co*SC + ph);
        if (co < 64) {
            #pragma unroll 4
            for (int j = 0; j < 16; j++) {
                if (w0 + ph + j*4 < W) {
                    float4 rv = *(const float4*)(rin + gb + j*4);
                    float4 dv = dp[j];
                    rv.x += dv.x; rv.y += dv.y; rv.z += dv.z; rv.w += dv.w;
                    *(float4*)(rout + gb + j*4) = rv;
                    float4 rt = make_float4(tf32r(rv.x), tf32r(rv.y), tf32r(rv.z), tf32r(rv.w));
                    *(float4*)(routT + gb + j*4) = rt;
                }
            }
        } else {
            #pragma unroll 4
            for (int j = 0; j < 16; j++) {
                if (w0 + ph + j*4 < W) {
                    float4 sv = *(const float4*)(g_skp + gb + j*4);
                    float4 dv = dp[j];
                    sv.x += dv.x; sv.y += dv.y; sv.z += dv.z; sv.w += dv.w;
                    *(float4*)(g_skp + gb + j*4) = sv;
                }
            }
        }
    }
}

// ---------------- post ----------------
__global__ void __launch_bounds__(256) post_kernel(const float* __restrict__ p1,
                                                   const float* __restrict__ p2,
                                                   const float* __restrict__ xext,
                                                   float* __restrict__ out, int flow)
{
    __shared__ float p1T[64*64];
    __shared__ float p2s[128];
    for (int i = threadIdx.x; i < 4096; i += 256) p1T[(i & 63)*64 + (i >> 6)] = p1[i];
    if (threadIdx.x < 128) p2s[threadIdx.x] = p2[threadIdx.x];
    __syncthreads();
    int pix = blockIdx.x * 256 + threadIdx.x;
    if (pix >= NPIX) return;
    int b = pix / PLANE, rem = pix - b * PLANE, h = rem / W, w = rem - (rem / W) * W;

    u64 h2[32];
    #pragma unroll
    for (int k = 0; k < 32; k++) h2[k] = 0ull;
    for (int j = 0; j < 64; j++) {
        float s = fmaxf(g_skp[((b*64 + j)*H + h)*W + w], 0.f);
        u64 ss = dup2(s);
        const ulonglong2* pr = (const ulonglong2*)(p1T + j*64);
        #pragma unroll
        for (int k2 = 0; k2 < 16; k2++) {
            ulonglong2 wv2 = pr[k2];
            ffma2(h2[2*k2], wv2.x, ss);
            ffma2(h2[2*k2+1], wv2.y, ss);
        }
    }
    float o0 = 0.f, o1 = 0.f;
    #pragma unroll
    for (int k = 0; k < 32; k++) {
        float lo, hi; unpk(h2[k], lo, hi);
        float a = fmaxf(lo, 0.f), bb = fmaxf(hi, 0.f);
        o0 = fmaf(p2s[2*k], a, o0);      o0 = fmaf(p2s[2*k+1], bb, o0);
        o1 = fmaf(p2s[64+2*k], a, o1);   o1 = fmaf(p2s[64+2*k+1], bb, o1);
    }
    float mean = o0, lv = fminf(o1, 10.f), e = expf(lv);
    float* gm = out + NPIX; float* gl = out + 2*NPIX;
    if (flow == 0) { gm[pix] = mean; gl[pix] = lv; }
    else           { gm[pix] = gm[pix]*e + mean; gl[pix] += lv; }
    const float* xs = (flow == 0) ? xext : g_xbuf[(flow + 1) & 1];
    float xn = e * xs[pix] + mean;
    int hd = (flow < 4) ? (15 - h) : (h < 8 ? 7 - h : 23 - h);
    int odx = b*PLANE + hd*W + w;
    g_xbuf[flow & 1][odx] = xn;
    if (flow == NFLOW - 1) out[odx] = xn;
}

// ---------------- host ----------------
extern "C" void kernel_launch(void* const* d_in, const int* in_sizes, int n_in,
                              void* d_out, int out_size)
{
    const float* x       = (const float*)d_in[0];
    const float* c       = (const float*)d_in[1];
    const float* first_w = (const float*)d_in[2];
    const float* init_w  = (const float*)d_in[3];
    const float* cdt_w   = (const float*)d_in[4];
    const float* res_w   = (const float*)d_in[5];
    const float* skp_w   = (const float*)d_in[6];
    const float* p1      = (const float*)d_in[7];
    const float* p2      = (const float*)d_in[8];
    float* out = (float*)d_out;

    const int SMEMB = SMEMF * 4;   // 108544 B -> 2 CTAs/SM
    cudaFuncSetAttribute(layer_kernel<1>, cudaFuncAttributeMaxDynamicSharedMemorySize, SMEMB);
    cudaFuncSetAttribute(layer_kernel<2>, cudaFuncAttributeMaxDynamicSharedMemorySize, SMEMB);
    cudaFuncSetAttribute(layer_kernel<4>, cudaFuncAttributeMaxDynamicSharedMemorySize, SMEMB);
    cudaFuncSetAttribute(layer_kernel<8>, cudaFuncAttributeMaxDynamicSharedMemorySize, SMEMB);

    long tot = (long)N1 + N2 + N3 + NC;
    prep_weights<<<(unsigned)((tot + 255) / 256), 256>>>(init_w, cdt_w, res_w, skp_w, c);

    dim3 gl((W + 127) / 128, B * H);   // (32, 32)
    for (int f = 0; f < NFLOW; f++) {
        first_conv<<<(NPIX + 255) / 256, 256>>>(first_w + f * 128, x, f);
        for (int l = 0; l < NLAYER; l++) {
            int d = 1 << (l & 3);
            int fl = f * NLAYER + l;
            int rb = l & 1;
            switch (d) {
                case 1:  layer_kernel<1><<<gl, 256, SMEMB>>>(f, fl, rb); break;
                case 2:  layer_kernel<2><<<gl, 256, SMEMB>>>(f, fl, rb); break;
                case 4:  layer_kernel<4><<<gl, 256, SMEMB>>>(f, fl, rb); break;
                default: layer_kernel<8><<<gl, 256, SMEMB>>>(f, fl, rb); break;
            }
        }
        post_kernel<<<(NPIX + 255) / 256, 256>>>(p1 + f * 64 * 64, p2 + f * 2 * 64, x, out, f);
    }
    (void)in_sizes; (void)n_in; (void)out_size;
}

// round 17
// speedup vs baseline: 1.0040x; 1.0040x over previous
#include <cuda_runtime.h>
#include <math.h>
#include <stdint.h>

#define B 2
#define H 16
#define W 4000
#define PLANE (H*W)
#define NPIX (B*PLANE)
#define CDT 80
#define NFLOW 8
#define NLAYER 8
typedef unsigned long long u64;
typedef unsigned int u32;

// smem layout (floats): [R1 9728][SML 8704][BIG 8704] = 27136 floats = 108544 B
#define SA 152
#define SBN 264          // interleaved weight row stride (256 used); 264%32=8 -> LDS.64 conflict-free
#define SC 136
#define SMLF 9728
#define BIGF 18432
#define SMEMF 27136

// ---------------- helpers ----------------
__device__ __forceinline__ u32 smem_u32(const void* p) {
    u32 a; asm("{ .reg .u64 t; cvta.to.shared.u64 t, %1; cvt.u32.u64 %0, t; }" : "=r"(a) : "l"(p));
    return a;
}
__device__ __forceinline__ float tf32r(float x) {
    u32 r; asm("cvt.rna.tf32.f32 %0, %1;" : "=r"(r) : "f"(x));
    return __uint_as_float(r);
}
__device__ __forceinline__ u64 dup2(float x) { u64 r; asm("mov.b64 %0, {%1, %1};" : "=l"(r) : "f"(x)); return r; }
__device__ __forceinline__ void ffma2(u64& d, u64 a, u64 b) { asm("fma.rn.f32x2 %0, %1, %2, %0;" : "+l"(d) : "l"(a), "l"(b)); }
__device__ __forceinline__ void unpk(u64 v, float& lo, float& hi) { asm("mov.b64 {%0, %1}, %2;" : "=f"(lo), "=f"(hi) : "l"(v)); }

#define CPA16(d, s)     asm volatile("cp.async.cg.shared.global [%0], [%1], 16;" :: "r"(d), "l"(s) : "memory")
#define CPA16Z(d, s, z) asm volatile("cp.async.cg.shared.global [%0], [%1], 16, %2;" :: "r"(d), "l"(s), "r"(z) : "memory")
#define CP_COMMIT() asm volatile("cp.async.commit_group;" ::: "memory")
#define CP_WAIT1()  asm volatile("cp.async.wait_group 1;" ::: "memory")
#define CP_WAIT0()  asm volatile("cp.async.wait_group 0;" ::: "memory")

__device__ __forceinline__ void mma8(float* d, const u32* a, u32 b0, u32 b1) {
    asm("mma.sync.aligned.m16n8k8.row.col.f32.tf32.tf32.f32 "
        "{%0,%1,%2,%3}, {%4,%5,%6,%7}, {%8,%9}, {%0,%1,%2,%3};"
        : "+f"(d[0]), "+f"(d[1]), "+f"(d[2]), "+f"(d[3])
        : "r"(a[0]), "r"(a[1]), "r"(a[2]), "r"(a[3]), "r"(b0), "r"(b1));
}

// one k8 chunk, 64x32 warp tile. A stored [k][m] stride sa.
// B stored pair-interleaved: row (k0/2 + kk) holds (k0+kk, k0+kk+4) pairs at cols (2n, 2n+1).
__device__ __forceinline__ void gemm_k8(float (&acc)[4][4][4],
    const float* As, int sa, const float* Bs, int k0, int pm, int pn, int gid, int tg)
{
    u32 a[4][4];
    const float* ar = As + (k0 + tg) * sa;
    #pragma unroll
    for (int ms = 0; ms < 4; ms++) {
        const float* ap = ar + pm + ms*16 + gid;
        a[ms][0] = __float_as_uint(ap[0]);
        a[ms][1] = __float_as_uint(ap[8]);
        a[ms][2] = __float_as_uint(ap[4*sa]);
        a[ms][3] = __float_as_uint(ap[4*sa + 8]);
    }
    const float2* br = (const float2*)(Bs + ((k0 >> 1) + tg) * SBN) + pn + gid;
    #pragma unroll
    for (int ns = 0; ns < 4; ns++) {
        float2 bb = br[ns*8];
        u32 b0 = __float_as_uint(bb.x);
        u32 b1 = __float_as_uint(bb.y);
        #pragma unroll
        for (int ms = 0; ms < 4; ms++) mma8(acc[ms][ns], a[ms], b0, b1);
    }
}

// ---------------- persistent scratch ----------------
__device__ __align__(16) float g_res2[2][B*64*PLANE];
__device__ __align__(16) float g_resT[2][B*64*PLANE];
__device__ __align__(16) float g_skp[B*64*PLANE];
__device__ __align__(16) float g_xbuf[2][NPIX];
__device__ __align__(16) float g_cT [B*CDT*PLANE];
__device__ __align__(16) float g_wT [NFLOW*NLAYER*9*8192];    // [fl][tap][32 rows][256] interleaved
__device__ __align__(16) float g_cwT[NFLOW*NLAYER*10240];     // [fl][40 rows][256] (2 halves x 20)
__device__ __align__(16) float g_uwT[NFLOW*NLAYER*8192];      // [fl][32 rows][256]

#define N1 (NFLOW*NLAYER*64*9*128)
#define N2 (NFLOW*NLAYER*CDT*128)
#define N3 (NFLOW*NLAYER*64*128)
#define NC (B*CDT*PLANE)

// g-column interleave: tanh ci -> 2ci, sigmoid ci -> 2ci+1
__device__ __forceinline__ int gperm(int co) { return (co < 64) ? 2*co : 2*(co - 64) + 1; }

__global__ void prep_weights(const float* __restrict__ iw, const float* __restrict__ cw,
                             const float* __restrict__ rw, const float* __restrict__ sw,
                             const float* __restrict__ cfull)
{
    long idx = (long)blockIdx.x * 256 + threadIdx.x;
    if (idx < N1) {
        int co  = (int)(idx & 127);
        long t  = idx >> 7;
        int tap = (int)(t % 9); t /= 9;
        int ci  = (int)(t & 63);
        int fl  = (int)(t >> 6);
        int kh = tap / 3, kw = tap % 3;
        int kc = ci >> 3, kk = ci & 7;
        long dst = (long)fl*73728 + (long)tap*8192
                 + (long)(kc*4 + (kk & 3))*256 + 2*gperm(co) + (kk >> 2);
        g_wT[dst] = tf32r(iw[((((long)fl*128 + co)*64 + ci)*3 + kh)*3 + kw]);
    } else if (idx < N1 + N2) {
        long i2 = idx - N1;
        int co = (int)(i2 & 127);
        long t = i2 >> 7;
        int ci = (int)(t % CDT);
        int fl = (int)(t / CDT);
        int half = ci / 40, lk = ci - half*40;
        int kc = lk >> 3, kk = lk & 7;
        long dst = (long)fl*10240 + (long)(half*20 + kc*4 + (kk & 3))*256 + 2*gperm(co) + (kk >> 2);
        g_cwT[dst] = tf32r(cw[((long)fl*128 + co)*CDT + ci]);
    } else if (idx < N1 + N2 + N3) {
        long i3 = idx - N1 - N2;
        int o  = (int)(i3 & 127);
        long t = i3 >> 7;
        int ci = (int)(t & 63);
        int fl = (int)(t >> 6);
        int kc = ci >> 3, kk = ci & 7;
        long dst = (long)fl*8192 + (long)(kc*4 + (kk & 3))*256 + 2*o + (kk >> 2);
        g_uwT[dst] = tf32r((o < 64) ? rw[((long)fl*64 + o)*64 + ci]
                                    : sw[((long)fl*64 + (o-64))*64 + ci]);
    } else if (idx < N1 + N2 + N3 + NC) {
        long i4 = idx - N1 - N2 - N3;
        g_cT[i4] = tf32r(cfull[i4]);
    }
}

// ---------------- first conv ----------------
__global__ void __launch_bounds__(256) first_conv(const float* __restrict__ fw,
                                                  const float* __restrict__ xext, int flow)
{
    __shared__ float fsh[128];
    if (threadIdx.x < 128) fsh[threadIdx.x] = fw[threadIdx.x];
    __syncthreads();
    int pix = blockIdx.x * 256 + threadIdx.x;
    if (pix >= NPIX) return;
    int b = pix / PLANE, rem = pix - b * PLANE, h = rem / W, w = rem - (rem / W) * W;
    const float* xs = (flow == 0) ? xext : g_xbuf[(flow + 1) & 1];
    float x2 = (h >= 2) ? xs[pix - 2*W] : 0.f;
    float x1 = (h >= 1) ? xs[pix - W]   : 0.f;
    #pragma unroll 4
    for (int o = 0; o < 64; o++) {
        float v = tanhf(fsh[2*o]*x2 + fsh[2*o+1]*x1);
        int idx = ((b*64 + o)*H + h)*W + w;
        g_res2[0][idx] = v;
        g_resT[0][idx] = tf32r(v);
        g_skp[idx] = 0.f;
    }
}

// ---------------- fused layer: warp-MMA tf32, interleaved-B LDS.64 ----------------
template<int D>
__global__ void __launch_bounds__(256, 2) layer_kernel(int flow, int fl, int rb)
{
    extern __shared__ __align__(16) float sh[];
    const int tid = threadIdx.x, lane = tid & 31, wq = tid >> 5;
    const int b = blockIdx.y >> 4, h = blockIdx.y & 15;
    const int w0 = blockIdx.x * 128;
    const int pm = (wq & 1) * 64, pn = (wq >> 1) * 32;
    const int gid = lane >> 2, tg = lane & 3;
    const float* rin  = g_res2[rb];
    const float* rinT = g_resT[rb];
    float* rout  = g_res2[rb ^ 1];
    float* routT = g_resT[rb ^ 1];
    const u32 shb = smem_u32(sh);

    const float* wA = g_wT + (long)fl*73728;
    const float* wC = g_cwT + (long)fl*10240;
    const float* wU = g_uwT + (long)fl*8192;

    int hm = h;
    #pragma unroll 1
    for (int j = flow - 1; j >= 0; j--)
        hm = (j < 4) ? (15 - hm) : (hm < 8 ? 7 - hm : 23 - hm);

    // stage rows2 interleaved weight rows (256 floats each) into slot
    auto stage_w = [&](u32 dst_off, const float* src, int rows2) {
        u32 dstb = shb + dst_off * 4;
        int nq = rows2 * 64;
        for (int q = tid; q < nq; q += 256) {
            int ci = q >> 6, jj = q & 63;
            CPA16(dstb + (u32)(ci*SBN + jj*4)*4, src + ci*256 + jj*4);
        }
        CP_COMMIT();
    };
    auto stage_A = [&](int hs) {     // caller may pass hs<0: empty commit (dead row)
        if (hs >= 0) {
            #pragma unroll 3
            for (int q = tid; q < 2304; q += 256) {
                int ci = q / 36, j = q - (q / 36) * 36;
                int wg = w0 + j*4 - 8;
                bool ok = (unsigned)wg < (unsigned)W;
                const float* src = rinT + ((long)(b*64 + ci)*H + hs)*W + (ok ? wg : 0);
                u32 z = ok ? 16u : 0u;
                CPA16Z(shb + (u32)(ci*SA + j*4)*4, src, z);
            }
        }
        CP_COMMIT();
    };
    auto stage_acts = [&](int ci0) {
        #pragma unroll 3
        for (int q = tid; q < 1280; q += 256) {
            int ci = q >> 5, j = q & 31;
            int wg = w0 + j*4;
            bool ok = wg < W;
            const float* src = g_cT + ((long)(b*CDT + ci0 + ci)*H + hm)*W + (ok ? wg : 0);
            u32 z = ok ? 16u : 0u;
            CPA16Z(shb + (u32)(ci*SC + j*4)*4, src, z);
        }
        CP_COMMIT();
    };
    auto slot = [&](int i) -> u32 { return (i & 1) ? BIGF : SMLF; };

    float acc[4][4][4];
    #pragma unroll
    for (int ms = 0; ms < 4; ms++)
        #pragma unroll
        for (int ns = 0; ns < 4; ns++)
            #pragma unroll
            for (int q = 0; q < 4; q++) acc[ms][ns][q] = 0.f;

    stage_A(h - 2*D);
    stage_w(SMLF, wA, 32);                       // tap 0

    // -------- 9 conv taps (MMA skipped when row dead; phases static) --------
    for (int r = 0; r < 3; r++) {
        const bool live = (h - (2 - r) * D) >= 0;
        #pragma unroll 1
        for (int kw = 0; kw < 3; kw++) {
            int i = 3*r + kw;
            if (i < 8)  stage_w(slot(i+1), wA + (long)(i+1)*8192, 32);
            else        stage_w(BIGF, wC, 20);   // cond W half 1
            CP_WAIT1();
            __syncthreads();
            if (live) {
                const float* As = sh + (kw - 1)*D + 8;
                const float* Bs = sh + slot(i);
                #pragma unroll 2
                for (int kc = 0; kc < 8; kc++) gemm_k8(acc, As, SA, Bs, kc*8, pm, pn, gid, tg);
            }
            __syncthreads();
        }
        if (r < 2) stage_A(h - (1 - r)*D);
    }

    // -------- conditioner (K=80), two 40-row halves --------
    stage_acts(0);
    stage_w(SMLF, wC + 20*256, 20);              // cond W half 2
    CP_WAIT1();
    __syncthreads();
    #pragma unroll 1
    for (int kc = 0; kc < 5; kc++) gemm_k8(acc, sh, SC, sh + BIGF, kc*8, pm, pn, gid, tg);
    __syncthreads();
    stage_acts(40);
    stage_w(BIGF, wU, 32);                       // update W
    CP_WAIT1();
    __syncthreads();
    #pragma unroll 1
    for (int kc = 5; kc < 10; kc++) gemm_k8(acc, sh, SC, sh + SMLF, kc*8 - 40, pm, pn, gid, tg);
    __syncthreads();

    // -------- gate in registers: c-frags hold (tanh, sigmoid) pairs --------
    #pragma unroll
    for (int ms = 0; ms < 4; ms++)
        #pragma unroll
        for (int ns = 0; ns < 4; ns++) {
            int px0 = pm + ms*16 + gid;
            int p   = (pn >> 1) + ns*4 + tg;
            float t0 = acc[ms][ns][0], s0 = acc[ms][ns][1];
            float t1 = acc[ms][ns][2], s1 = acc[ms][ns][3];
            float v0 = (1.f - __fdividef(2.f, 1.f + __expf(2.f*t0))) *
                       __fdividef(1.f, 1.f + __expf(-s0));
            float v1 = (1.f - __fdividef(2.f, 1.f + __expf(2.f*t1))) *
                       __fdividef(1.f, 1.f + __expf(-s1));
            sh[p*SC + px0]     = tf32r(v0);
            sh[p*SC + px0 + 8] = tf32r(v1);
            acc[ms][ns][0] = acc[ms][ns][1] = acc[ms][ns][2] = acc[ms][ns][3] = 0.f;
        }
    CP_WAIT0();                              // update weights arrived
    __syncthreads();

    // -------- update GEMM: D2[px][o] = act @ [rw|sw] --------
    #pragma unroll 2
    for (int kc = 0; kc < 8; kc++) gemm_k8(acc, sh, SC, sh + BIGF, kc*8, pm, pn, gid, tg);
    __syncthreads();
    float* d2 = sh + SMLF;
    #pragma unroll
    for (int ms = 0; ms < 4; ms++)
        #pragma unroll
        for (int ns = 0; ns < 4; ns++) {
            int px0 = pm + ms*16 + gid, co0 = pn + ns*8 + tg*2;
            d2[co0*SC + px0]         = acc[ms][ns][0];
            d2[(co0+1)*SC + px0]     = acc[ms][ns][1];
            d2[co0*SC + px0 + 8]     = acc[ms][ns][2];
            d2[(co0+1)*SC + px0 + 8] = acc[ms][ns][3];
        }
    __syncthreads();

    // writeout
    {
        int co = tid >> 1;
        int ph = (tid & 1) * 64;
        int ch = co & 63;
        long gb = ((long)(b*64 + ch)*H + h)*W + w0 + ph;
        const float4* dp = (const float4*)(d2 + co*SC + ph);
        if (co < 64) {
            #pragma unroll 4
            for (int j = 0; j < 16; j++) {
                if (w0 + ph + j*4 < W) {
                    float4 rv = *(const float4*)(rin + gb + j*4);
                    float4 dv = dp[j];
                    rv.x += dv.x; rv.y += dv.y; rv.z += dv.z; rv.w += dv.w;
                    *(float4*)(rout + gb + j*4) = rv;
                    float4 rt = make_float4(tf32r(rv.x), tf32r(rv.y), tf32r(rv.z), tf32r(rv.w));
                    *(float4*)(routT + gb + j*4) = rt;
                }
            }
        } else {
            #pragma unroll 4
            for (int j = 0; j < 16; j++) {
                if (w0 + ph + j*4 < W) {
                    float4 sv = *(const float4*)(g_skp + gb + j*4);
                    float4 dv = dp[j];
                    sv.x += dv.x; sv.y += dv.y; sv.z += dv.z; sv.w += dv.w;
                    *(float4*)(g_skp + gb + j*4) = sv;
                }
            }
        }
    }
}

// ---------------- post ----------------
__global__ void __launch_bounds__(256) post_kernel(const float* __restrict__ p1,
                                                   const float* __restrict__ p2,
                                                   const float* __restrict__ xext,
                                                   float* __restrict__ out, int flow)
{
    __shared__ float p1T[64*64];
    __shared__ float p2s[128];
    for (int i = threadIdx.x; i < 4096; i += 256) p1T[(i & 63)*64 + (i >> 6)] = p1[i];
    if (threadIdx.x < 128) p2s[threadIdx.x] = p2[threadIdx.x];
    __syncthreads();
    int pix = blockIdx.x * 256 + threadIdx.x;
    if (pix >= NPIX) return;
    int b = pix / PLANE, rem = pix - b * PLANE, h = rem / W, w = rem - (rem / W) * W;

    u64 h2[32];
    #pragma unroll
    for (int k = 0; k < 32; k++) h2[k] = 0ull;
    for (int j = 0; j < 64; j++) {
        float s = fmaxf(g_skp[((b*64 + j)*H + h)*W + w], 0.f);
        u64 ss = dup2(s);
        const ulonglong2* pr = (const ulonglong2*)(p1T + j*64);
        #pragma unroll
        for (int k2 = 0; k2 < 16; k2++) {
            ulonglong2 wv2 = pr[k2];
            ffma2(h2[2*k2], wv2.x, ss);
            ffma2(h2[2*k2+1], wv2.y, ss);
        }
    }
    float o0 = 0.f, o1 = 0.f;
    #pragma unroll
    for (int k = 0; k < 32; k++) {
        float lo, hi; unpk(h2[k], lo, hi);
        float a = fmaxf(lo, 0.f), bb = fmaxf(hi, 0.f);
        o0 = fmaf(p2s[2*k], a, o0);      o0 = fmaf(p2s[2*k+1], bb, o0);
        o1 = fmaf(p2s[64+2*k], a, o1);   o1 = fmaf(p2s[64+2*k+1], bb, o1);
    }
    float mean = o0, lv = fminf(o1, 10.f), e = expf(lv);
    float* gm = out + NPIX; float* gl = out + 2*NPIX;
    if (flow == 0) { gm[pix] = mean; gl[pix] = lv; }
    else           { gm[pix] = gm[pix]*e + mean; gl[pix] += lv; }
    const float* xs = (flow == 0) ? xext : g_xbuf[(flow + 1) & 1];
    float xn = e * xs[pix] + mean;
    int hd = (flow < 4) ? (15 - h) : (h < 8 ? 7 - h : 23 - h);
    int odx = b*PLANE + hd*W + w;
    g_xbuf[flow & 1][odx] = xn;
    if (flow == NFLOW - 1) out[odx] = xn;
}

// ---------------- host ----------------
extern "C" void kernel_launch(void* const* d_in, const int* in_sizes, int n_in,
                              void* d_out, int out_size)
{
    const float* x       = (const float*)d_in[0];
    const float* c       = (const float*)d_in[1];
    const float* first_w = (const float*)d_in[2];
    const float* init_w  = (const float*)d_in[3];
    const float* cdt_w   = (const float*)d_in[4];
    const float* res_w   = (const float*)d_in[5];
    const float* skp_w   = (const float*)d_in[6];
    const float* p1      = (const float*)d_in[7];
    const float* p2      = (const float*)d_in[8];
    float* out = (float*)d_out;

    const int SMEMB = SMEMF * 4;   // 108544 B -> 2 CTAs/SM
    cudaFuncSetAttribute(layer_kernel<1>, cudaFuncAttributeMaxDynamicSharedMemorySize, SMEMB);
    cudaFuncSetAttribute(layer_kernel<2>, cudaFuncAttributeMaxDynamicSharedMemorySize, SMEMB);
    cudaFuncSetAttribute(layer_kernel<4>, cudaFuncAttributeMaxDynamicSharedMemorySize, SMEMB);
    cudaFuncSetAttribute(layer_kernel<8>, cudaFuncAttributeMaxDynamicSharedMemorySize, SMEMB);

    long tot = (long)N1 + N2 + N3 + NC;
    prep_weights<<<(unsigned)((tot + 255) / 256), 256>>>(init_w, cdt_w, res_w, skp_w, c);

    dim3 gl((W + 127) / 128, B * H);   // (32, 32)
    for (int f = 0; f < NFLOW; f++) {
        first_conv<<<(NPIX + 255) / 256, 256>>>(first_w + f * 128, x, f);
        for (int l = 0; l < NLAYER; l++) {
            int d = 1 << (l & 3);
            int fl = f * NLAYER + l;
            int rb = l & 1;
            switch (d) {
                case 1:  layer_kernel<1><<<gl, 256, SMEMB>>>(f, fl, rb); break;
                case 2:  layer_kernel<2><<<gl, 256, SMEMB>>>(f, fl, rb); break;
                case 4:  layer_kernel<4><<<gl, 256, SMEMB>>>(f, fl, rb); break;
                default: layer_kernel<8><<<gl, 256, SMEMB>>>(f, fl, rb); break;
            }
        }
        post_kernel<<<(NPIX + 255) / 256, 256>>>(p1 + f * 64 * 64, p2 + f * 2 * 64, x, out, f);
    }
    (void)in_sizes; (void)n_in; (void)out_size;
}